// round 1
// baseline (speedup 1.0000x reference)
#include <cuda_runtime.h>

#define B_   4
#define N_   40
#define NC   64000      // 40^3
#define RT   256000     // B * N^3
#define F_   128
#define H_   128

// scratch (device globals per allocation rules)
__device__ float g_xembed[(size_t)RT * H_];
__device__ float g_sumexp[B_ * H_];
__device__ int   g_len[B_];

// ---------------------------------------------------------------------------
// Kernel 0: decode mask -> per-batch lengths, zero softmax denominators.
// Mask may arrive as 1-byte bool or 4-byte int/float; mask[0][1] is always
// true (lengths >= 20), so byte[1]==0 implies a 4-byte element layout.
// ---------------------------------------------------------------------------
__global__ void k_setup(const unsigned char* __restrict__ mraw) {
    int t = threadIdx.x;
    if (t < B_ * H_) g_sumexp[t] = 0.f;
    if (t < B_) {
        int cnt = 0;
        if (mraw[1] != 0) {
            // byte-wise bool layout
            for (int j = 0; j < N_; j++) cnt += (mraw[t * N_ + j] != 0) ? 1 : 0;
        } else {
            // 32-bit element layout (int32 or float32: nonzero bits == true)
            const unsigned int* mi = (const unsigned int*)mraw;
            for (int j = 0; j < N_; j++) cnt += (mi[t * N_ + j] != 0u) ? 1 : 0;
        }
        g_len[t] = cnt;
    }
}

// ---------------------------------------------------------------------------
// Kernel 1: x_embed = relu(x @ Wi1 + bi1) @ Wi2 + bi2 for all 256000 rows.
// Also accumulates sum of exp(logit) per (batch, channel) over valid rows.
// Tile: 64 rows x 128 cols, 256 threads. Thread = (warp wg: rows wg*8..+7,
// lane cg: cols 4*cg..+3). A-operand broadcast from smem, W streamed (L2-hot).
// ---------------------------------------------------------------------------
__global__ __launch_bounds__(256) void k_embed(
    const float* __restrict__ x,
    const float* __restrict__ Wi1, const float* __restrict__ bi1,
    const float* __restrict__ Wi2, const float* __restrict__ bi2)
{
    __shared__ float sA[64 * 128];
    __shared__ float sSum[128];

    const int row0 = blockIdx.x * 64;     // 64000 % 64 == 0 -> no batch straddle
    const int b    = row0 / NC;
    const int t    = threadIdx.x;
    const int cg   = t & 31;
    const int wg   = t >> 5;
    const int c0   = cg * 4;

    // load x tile (rows are contiguous, F=128 innermost)
    {
        const float4* xg = (const float4*)(x + (size_t)row0 * F_);
        float4* s4 = (float4*)sA;
        #pragma unroll
        for (int i = 0; i < 8; i++) s4[t + i * 256] = xg[t + i * 256];
    }
    if (t < 128) sSum[t] = 0.f;
    __syncthreads();

    float4 acc[8];

    // ---- GEMM1: y1 = relu(x @ Wi1 + bi1) ----
    {
        float4 bias = *(const float4*)(bi1 + c0);
        #pragma unroll
        for (int m = 0; m < 8; m++) acc[m] = bias;
    }
    for (int k = 0; k < 128; k += 4) {
        float4 w0 = *(const float4*)(Wi1 + (k + 0) * 128 + c0);
        float4 w1 = *(const float4*)(Wi1 + (k + 1) * 128 + c0);
        float4 w2 = *(const float4*)(Wi1 + (k + 2) * 128 + c0);
        float4 w3 = *(const float4*)(Wi1 + (k + 3) * 128 + c0);
        #pragma unroll
        for (int m = 0; m < 8; m++) {
            float4 av = *(const float4*)(&sA[(wg * 8 + m) * 128 + k]);
            acc[m].x += av.x * w0.x + av.y * w1.x + av.z * w2.x + av.w * w3.x;
            acc[m].y += av.x * w0.y + av.y * w1.y + av.z * w2.y + av.w * w3.y;
            acc[m].z += av.x * w0.z + av.y * w1.z + av.z * w2.z + av.w * w3.z;
            acc[m].w += av.x * w0.w + av.y * w1.w + av.z * w2.w + av.w * w3.w;
        }
    }
    __syncthreads();   // done reading x tile
    #pragma unroll
    for (int m = 0; m < 8; m++) {
        float4 r;
        r.x = fmaxf(acc[m].x, 0.f);
        r.y = fmaxf(acc[m].y, 0.f);
        r.z = fmaxf(acc[m].z, 0.f);
        r.w = fmaxf(acc[m].w, 0.f);
        *(float4*)(&sA[(wg * 8 + m) * 128 + c0]) = r;  // overwrite tile with y1
    }
    __syncthreads();

    // ---- GEMM2: y2 = y1 @ Wi2 + bi2 ----
    {
        float4 bias = *(const float4*)(bi2 + c0);
        #pragma unroll
        for (int m = 0; m < 8; m++) acc[m] = bias;
    }
    for (int k = 0; k < 128; k += 4) {
        float4 w0 = *(const float4*)(Wi2 + (k + 0) * 128 + c0);
        float4 w1 = *(const float4*)(Wi2 + (k + 1) * 128 + c0);
        float4 w2 = *(const float4*)(Wi2 + (k + 2) * 128 + c0);
        float4 w3 = *(const float4*)(Wi2 + (k + 3) * 128 + c0);
        #pragma unroll
        for (int m = 0; m < 8; m++) {
            float4 av = *(const float4*)(&sA[(wg * 8 + m) * 128 + k]);
            acc[m].x += av.x * w0.x + av.y * w1.x + av.z * w2.x + av.w * w3.x;
            acc[m].y += av.x * w0.y + av.y * w1.y + av.z * w2.y + av.w * w3.y;
            acc[m].z += av.x * w0.z + av.y * w1.z + av.z * w2.z + av.w * w3.z;
            acc[m].w += av.x * w0.w + av.y * w1.w + av.z * w2.w + av.w * w3.w;
        }
    }

    // ---- store x_embed + accumulate sumexp over valid hyperedges ----
    const int lenb = g_len[b];
    float4 es = make_float4(0.f, 0.f, 0.f, 0.f);
    bool any = false;
    #pragma unroll
    for (int m = 0; m < 8; m++) {
        const int row = row0 + wg * 8 + m;
        *(float4*)(g_xembed + (size_t)row * 128 + c0) = acc[m];
        const int rem = row - b * NC;
        const int i  = rem / 1600;
        const int j  = (rem / 40) % 40;
        const int kk = rem % 40;
        if (i < j && j < kk && kk < lenb) {
            es.x += __expf(acc[m].x);
            es.y += __expf(acc[m].y);
            es.z += __expf(acc[m].z);
            es.w += __expf(acc[m].w);
            any = true;
        }
    }
    if (any) {
        atomicAdd(&sSum[c0 + 0], es.x);
        atomicAdd(&sSum[c0 + 1], es.y);
        atomicAdd(&sSum[c0 + 2], es.z);
        atomicAdd(&sSum[c0 + 3], es.w);
    }
    __syncthreads();
    if (t < 128) {
        float v = sSum[t];
        if (v != 0.f) atomicAdd(&g_sumexp[b * 128 + t], v);
    }
}

// ---------------------------------------------------------------------------
// Kernel 2: out = relu([a * relu(xf@We), xf] @ Wo1 + bo1) @ Wo2 + bo2
// a = valid ? exp(xf)/sumexp : 0.  The We GEMM and the top-half Wo1 k-loop
// are skipped per-warp when none of the warp's 8 rows is valid (~90% skip).
// ---------------------------------------------------------------------------
extern __shared__ float smem2[];
__global__ __launch_bounds__(256) void k_out(
    const float* __restrict__ We,
    const float* __restrict__ Wo1, const float* __restrict__ bo1,
    const float* __restrict__ Wo2, const float* __restrict__ bo2,
    float* __restrict__ out)
{
    float* sXF  = smem2;                 // 64*128
    float* sAXI = smem2 + 64 * 128;      // 64*128
    float* sInv = smem2 + 2 * 64 * 128;  // 128

    const int row0 = blockIdx.x * 64;
    const int b    = row0 / NC;
    const int t    = threadIdx.x;
    const int cg   = t & 31;
    const int wg   = t >> 5;
    const int c0   = cg * 4;

    {
        const float4* xg = (const float4*)(g_xembed + (size_t)row0 * 128);
        float4* s4 = (float4*)sXF;
        #pragma unroll
        for (int i = 0; i < 8; i++) s4[t + i * 256] = xg[t + i * 256];
    }
    if (t < 128) sInv[t] = 1.0f / g_sumexp[b * 128 + t];
    __syncthreads();

    // warp-uniform validity of this warp's 8 rows
    const int lenb = g_len[b];
    bool valid[8];
    bool any = false;
    #pragma unroll
    for (int m = 0; m < 8; m++) {
        const int rem = row0 + wg * 8 + m - b * NC;
        const int i  = rem / 1600;
        const int j  = (rem / 40) % 40;
        const int kk = rem % 40;
        valid[m] = (i < j) && (j < kk) && (kk < lenb);
        any |= valid[m];
    }

    // ---- stage A (valid warps only): axi = a .* relu(xf @ We) ----
    if (any) {
        float4 acc[8];
        #pragma unroll
        for (int m = 0; m < 8; m++) acc[m] = make_float4(0.f, 0.f, 0.f, 0.f);
        for (int k = 0; k < 128; k += 4) {
            float4 w0 = *(const float4*)(We + (k + 0) * 128 + c0);
            float4 w1 = *(const float4*)(We + (k + 1) * 128 + c0);
            float4 w2 = *(const float4*)(We + (k + 2) * 128 + c0);
            float4 w3 = *(const float4*)(We + (k + 3) * 128 + c0);
            #pragma unroll
            for (int m = 0; m < 8; m++) {
                float4 av = *(const float4*)(&sXF[(wg * 8 + m) * 128 + k]);
                acc[m].x += av.x * w0.x + av.y * w1.x + av.z * w2.x + av.w * w3.x;
                acc[m].y += av.x * w0.y + av.y * w1.y + av.z * w2.y + av.w * w3.y;
                acc[m].z += av.x * w0.z + av.y * w1.z + av.z * w2.z + av.w * w3.z;
                acc[m].w += av.x * w0.w + av.y * w1.w + av.z * w2.w + av.w * w3.w;
            }
        }
        float4 inv4 = *(const float4*)(&sInv[c0]);
        #pragma unroll
        for (int m = 0; m < 8; m++) {
            const int row = wg * 8 + m;
            float4 v = make_float4(0.f, 0.f, 0.f, 0.f);
            if (valid[m]) {
                float4 xfv = *(const float4*)(&sXF[row * 128 + c0]);
                v.x = __expf(xfv.x) * inv4.x * fmaxf(acc[m].x, 0.f);
                v.y = __expf(xfv.y) * inv4.y * fmaxf(acc[m].y, 0.f);
                v.z = __expf(xfv.z) * inv4.z * fmaxf(acc[m].z, 0.f);
                v.w = __expf(xfv.w) * inv4.w * fmaxf(acc[m].w, 0.f);
            }
            *(float4*)(&sAXI[row * 128 + c0]) = v;
        }
        __syncwarp();
    }

    // ---- stage B: g = relu(h @ Wo1 + bo1); out = g @ Wo2 + bo2 ----
    float rsum[8];
    #pragma unroll
    for (int m = 0; m < 8; m++) rsum[m] = 0.f;

    #pragma unroll
    for (int half = 0; half < 2; half++) {
        const int n0 = half * 128 + c0;
        float4 g[8];
        {
            float4 bias = *(const float4*)(bo1 + n0);
            #pragma unroll
            for (int m = 0; m < 8; m++) g[m] = bias;
        }
        // xf part: Wo1 rows 128..255
        for (int k = 0; k < 128; k += 4) {
            float4 w0 = *(const float4*)(Wo1 + (128 + k + 0) * 256 + n0);
            float4 w1 = *(const float4*)(Wo1 + (128 + k + 1) * 256 + n0);
            float4 w2 = *(const float4*)(Wo1 + (128 + k + 2) * 256 + n0);
            float4 w3 = *(const float4*)(Wo1 + (128 + k + 3) * 256 + n0);
            #pragma unroll
            for (int m = 0; m < 8; m++) {
                float4 av = *(const float4*)(&sXF[(wg * 8 + m) * 128 + k]);
                g[m].x += av.x * w0.x + av.y * w1.x + av.z * w2.x + av.w * w3.x;
                g[m].y += av.x * w0.y + av.y * w1.y + av.z * w2.y + av.w * w3.y;
                g[m].z += av.x * w0.z + av.y * w1.z + av.z * w2.z + av.w * w3.z;
                g[m].w += av.x * w0.w + av.y * w1.w + av.z * w2.w + av.w * w3.w;
            }
        }
        // a*x_inner part: Wo1 rows 0..127 (skipped when no valid row)
        if (any) {
            for (int k = 0; k < 128; k += 4) {
                float4 w0 = *(const float4*)(Wo1 + (k + 0) * 256 + n0);
                float4 w1 = *(const float4*)(Wo1 + (k + 1) * 256 + n0);
                float4 w2 = *(const float4*)(Wo1 + (k + 2) * 256 + n0);
                float4 w3 = *(const float4*)(Wo1 + (k + 3) * 256 + n0);
                #pragma unroll
                for (int m = 0; m < 8; m++) {
                    float4 av = *(const float4*)(&sAXI[(wg * 8 + m) * 128 + k]);
                    g[m].x += av.x * w0.x + av.y * w1.x + av.z * w2.x + av.w * w3.x;
                    g[m].y += av.x * w0.y + av.y * w1.y + av.z * w2.y + av.w * w3.y;
                    g[m].z += av.x * w0.z + av.y * w1.z + av.z * w2.z + av.w * w3.z;
                    g[m].w += av.x * w0.w + av.y * w1.w + av.z * w2.w + av.w * w3.w;
                }
            }
        }
        float4 w2v = *(const float4*)(Wo2 + n0);
        #pragma unroll
        for (int m = 0; m < 8; m++) {
            rsum[m] += fmaxf(g[m].x, 0.f) * w2v.x + fmaxf(g[m].y, 0.f) * w2v.y
                     + fmaxf(g[m].z, 0.f) * w2v.z + fmaxf(g[m].w, 0.f) * w2v.w;
        }
    }

    // warp reduction across the 32 column-lanes
    #pragma unroll
    for (int off = 16; off; off >>= 1) {
        #pragma unroll
        for (int m = 0; m < 8; m++)
            rsum[m] += __shfl_xor_sync(0xffffffffu, rsum[m], off);
    }
    if (cg == 0) {
        const float b2 = bo2[0];
        #pragma unroll
        for (int m = 0; m < 8; m++)
            out[row0 + wg * 8 + m] = rsum[m] + b2;
    }
}

// ---------------------------------------------------------------------------
extern "C" void kernel_launch(void* const* d_in, const int* in_sizes, int n_in,
                              void* d_out, int out_size) {
    const float* x          = (const float*)d_in[0];
    const unsigned char* mk = (const unsigned char*)d_in[1];
    const float* Wi1        = (const float*)d_in[2];
    const float* bi1        = (const float*)d_in[3];
    const float* Wi2        = (const float*)d_in[4];
    const float* bi2        = (const float*)d_in[5];
    const float* We         = (const float*)d_in[6];
    const float* Wo1        = (const float*)d_in[7];
    const float* bo1        = (const float*)d_in[8];
    const float* Wo2        = (const float*)d_in[9];
    const float* bo2        = (const float*)d_in[10];
    float* out              = (float*)d_out;

    const int smem_k_out = (2 * 64 * 128 + 128) * (int)sizeof(float);  // 66 KB
    cudaFuncSetAttribute(k_out, cudaFuncAttributeMaxDynamicSharedMemorySize, smem_k_out);

    k_setup<<<1, 512>>>(mk);
    k_embed<<<RT / 64, 256>>>(x, Wi1, bi1, Wi2, bi2);
    k_out<<<RT / 64, 256, smem_k_out>>>(We, Wo1, bo1, Wo2, bo2, out);
}

// round 2
// speedup vs baseline: 1.0446x; 1.0446x over previous
#include <cuda_runtime.h>

#define B_   4
#define N_   40
#define NC   64000      // 40^3
#define RT   256000     // B * N^3
#define F_   128
#define H_   128

// scratch (device globals per allocation rules)
__device__ float g_xembed[(size_t)RT * H_];
__device__ float g_sumexp[B_ * H_];
__device__ int   g_len[B_];

// ---- packed f32x2 helpers (sm_103a FFMA2: 2 fp32 MACs per issue slot) ----
typedef unsigned long long u64;

static __device__ __forceinline__ u64 pack_bcast(float s) {
    u64 r;
    asm("mov.b64 %0, {%1, %1};" : "=l"(r) : "f"(s));
    return r;
}
static __device__ __forceinline__ void ffma2(u64& d, u64 a, u64 b) {
    asm("fma.rn.f32x2 %0, %1, %2, %0;" : "+l"(d) : "l"(a), "l"(b));
}
static __device__ __forceinline__ float2 unpack2(u64 v) {
    float2 f;
    asm("mov.b64 {%0, %1}, %2;" : "=f"(f.x), "=f"(f.y) : "l"(v));
    return f;
}

// one packed GEMM micro-step: acc[m][0..1] (cols c0..c0+3) += A(row,k..k+3) * W(k..k+3, c0..c0+3)
#define GEMM_STEP_F2(ACC, AV, W0, W1, W2, W3)            \
    do {                                                  \
        u64 _ax = pack_bcast((AV).x);                     \
        u64 _ay = pack_bcast((AV).y);                     \
        u64 _az = pack_bcast((AV).z);                     \
        u64 _aw = pack_bcast((AV).w);                     \
        ffma2((ACC)[0], _ax, (W0).x);                     \
        ffma2((ACC)[1], _ax, (W0).y);                     \
        ffma2((ACC)[0], _ay, (W1).x);                     \
        ffma2((ACC)[1], _ay, (W1).y);                     \
        ffma2((ACC)[0], _az, (W2).x);                     \
        ffma2((ACC)[1], _az, (W2).y);                     \
        ffma2((ACC)[0], _aw, (W3).x);                     \
        ffma2((ACC)[1], _aw, (W3).y);                     \
    } while (0)

// ---------------------------------------------------------------------------
// Kernel 0: decode mask -> per-batch lengths, zero softmax denominators.
// ---------------------------------------------------------------------------
__global__ void k_setup(const unsigned char* __restrict__ mraw) {
    int t = threadIdx.x;
    if (t < B_ * H_) g_sumexp[t] = 0.f;
    if (t < B_) {
        int cnt = 0;
        if (mraw[1] != 0) {
            for (int j = 0; j < N_; j++) cnt += (mraw[t * N_ + j] != 0) ? 1 : 0;
        } else {
            const unsigned int* mi = (const unsigned int*)mraw;
            for (int j = 0; j < N_; j++) cnt += (mi[t * N_ + j] != 0u) ? 1 : 0;
        }
        g_len[t] = cnt;
    }
}

// ---------------------------------------------------------------------------
// Kernel 1: x_embed = relu(x @ Wi1 + bi1) @ Wi2 + bi2, + sumexp accumulation.
// 64x128 tile, 256 threads; inner GEMMs use packed f32x2 FMA.
// ---------------------------------------------------------------------------
__global__ __launch_bounds__(256) void k_embed(
    const float* __restrict__ x,
    const float* __restrict__ Wi1, const float* __restrict__ bi1,
    const float* __restrict__ Wi2, const float* __restrict__ bi2)
{
    __shared__ float sA[64 * 128];
    __shared__ float sSum[128];

    const int row0 = blockIdx.x * 64;
    const int b    = row0 / NC;
    const int t    = threadIdx.x;
    const int cg   = t & 31;
    const int wg   = t >> 5;
    const int c0   = cg * 4;

    {
        const float4* xg = (const float4*)(x + (size_t)row0 * F_);
        float4* s4 = (float4*)sA;
        #pragma unroll
        for (int i = 0; i < 8; i++) s4[t + i * 256] = xg[t + i * 256];
    }
    if (t < 128) sSum[t] = 0.f;
    __syncthreads();

    u64 acc[8][2];

    // ---- GEMM1: y1 = relu(x @ Wi1 + bi1) ----
    {
        ulonglong2 bias = *(const ulonglong2*)(bi1 + c0);
        #pragma unroll
        for (int m = 0; m < 8; m++) { acc[m][0] = bias.x; acc[m][1] = bias.y; }
    }
    for (int k = 0; k < 128; k += 4) {
        ulonglong2 w0 = *(const ulonglong2*)(Wi1 + (k + 0) * 128 + c0);
        ulonglong2 w1 = *(const ulonglong2*)(Wi1 + (k + 1) * 128 + c0);
        ulonglong2 w2 = *(const ulonglong2*)(Wi1 + (k + 2) * 128 + c0);
        ulonglong2 w3 = *(const ulonglong2*)(Wi1 + (k + 3) * 128 + c0);
        #pragma unroll
        for (int m = 0; m < 8; m++) {
            float4 av = *(const float4*)(&sA[(wg * 8 + m) * 128 + k]);
            GEMM_STEP_F2(acc[m], av, w0, w1, w2, w3);
        }
    }
    __syncthreads();
    #pragma unroll
    for (int m = 0; m < 8; m++) {
        float2 lo = unpack2(acc[m][0]);
        float2 hi = unpack2(acc[m][1]);
        float4 r;
        r.x = fmaxf(lo.x, 0.f);
        r.y = fmaxf(lo.y, 0.f);
        r.z = fmaxf(hi.x, 0.f);
        r.w = fmaxf(hi.y, 0.f);
        *(float4*)(&sA[(wg * 8 + m) * 128 + c0]) = r;
    }
    __syncthreads();

    // ---- GEMM2: y2 = y1 @ Wi2 + bi2 ----
    {
        ulonglong2 bias = *(const ulonglong2*)(bi2 + c0);
        #pragma unroll
        for (int m = 0; m < 8; m++) { acc[m][0] = bias.x; acc[m][1] = bias.y; }
    }
    for (int k = 0; k < 128; k += 4) {
        ulonglong2 w0 = *(const ulonglong2*)(Wi2 + (k + 0) * 128 + c0);
        ulonglong2 w1 = *(const ulonglong2*)(Wi2 + (k + 1) * 128 + c0);
        ulonglong2 w2 = *(const ulonglong2*)(Wi2 + (k + 2) * 128 + c0);
        ulonglong2 w3 = *(const ulonglong2*)(Wi2 + (k + 3) * 128 + c0);
        #pragma unroll
        for (int m = 0; m < 8; m++) {
            float4 av = *(const float4*)(&sA[(wg * 8 + m) * 128 + k]);
            GEMM_STEP_F2(acc[m], av, w0, w1, w2, w3);
        }
    }

    // ---- store x_embed + accumulate sumexp over valid hyperedges ----
    const int lenb = g_len[b];
    float4 es = make_float4(0.f, 0.f, 0.f, 0.f);
    bool any = false;
    #pragma unroll
    for (int m = 0; m < 8; m++) {
        const int row = row0 + wg * 8 + m;
        float2 lo = unpack2(acc[m][0]);
        float2 hi = unpack2(acc[m][1]);
        float4 v = make_float4(lo.x, lo.y, hi.x, hi.y);
        *(float4*)(g_xembed + (size_t)row * 128 + c0) = v;
        const int rem = row - b * NC;
        const int i  = rem / 1600;
        const int j  = (rem / 40) % 40;
        const int kk = rem % 40;
        if (i < j && j < kk && kk < lenb) {
            es.x += __expf(v.x);
            es.y += __expf(v.y);
            es.z += __expf(v.z);
            es.w += __expf(v.w);
            any = true;
        }
    }
    if (any) {
        atomicAdd(&sSum[c0 + 0], es.x);
        atomicAdd(&sSum[c0 + 1], es.y);
        atomicAdd(&sSum[c0 + 2], es.z);
        atomicAdd(&sSum[c0 + 3], es.w);
    }
    __syncthreads();
    if (t < 128) {
        float v = sSum[t];
        if (v != 0.f) atomicAdd(&g_sumexp[b * 128 + t], v);
    }
}

// ---------------------------------------------------------------------------
// Kernel 2: out = relu([a * relu(xf@We), xf] @ Wo1 + bo1) @ Wo2 + bo2
// ---------------------------------------------------------------------------
extern __shared__ float smem2[];
__global__ __launch_bounds__(256) void k_out(
    const float* __restrict__ We,
    const float* __restrict__ Wo1, const float* __restrict__ bo1,
    const float* __restrict__ Wo2, const float* __restrict__ bo2,
    float* __restrict__ out)
{
    float* sXF  = smem2;                 // 64*128
    float* sAXI = smem2 + 64 * 128;      // 64*128
    float* sInv = smem2 + 2 * 64 * 128;  // 128

    const int row0 = blockIdx.x * 64;
    const int b    = row0 / NC;
    const int t    = threadIdx.x;
    const int cg   = t & 31;
    const int wg   = t >> 5;
    const int c0   = cg * 4;

    {
        const float4* xg = (const float4*)(g_xembed + (size_t)row0 * 128);
        float4* s4 = (float4*)sXF;
        #pragma unroll
        for (int i = 0; i < 8; i++) s4[t + i * 256] = xg[t + i * 256];
    }
    if (t < 128) sInv[t] = 1.0f / g_sumexp[b * 128 + t];
    __syncthreads();

    const int lenb = g_len[b];
    bool valid[8];
    bool any = false;
    #pragma unroll
    for (int m = 0; m < 8; m++) {
        const int rem = row0 + wg * 8 + m - b * NC;
        const int i  = rem / 1600;
        const int j  = (rem / 40) % 40;
        const int kk = rem % 40;
        valid[m] = (i < j) && (j < kk) && (kk < lenb);
        any |= valid[m];
    }

    // ---- stage A (valid warps only): axi = a .* relu(xf @ We) ----
    if (any) {
        u64 acc[8][2];
        #pragma unroll
        for (int m = 0; m < 8; m++) { acc[m][0] = 0ull; acc[m][1] = 0ull; }
        for (int k = 0; k < 128; k += 4) {
            ulonglong2 w0 = *(const ulonglong2*)(We + (k + 0) * 128 + c0);
            ulonglong2 w1 = *(const ulonglong2*)(We + (k + 1) * 128 + c0);
            ulonglong2 w2 = *(const ulonglong2*)(We + (k + 2) * 128 + c0);
            ulonglong2 w3 = *(const ulonglong2*)(We + (k + 3) * 128 + c0);
            #pragma unroll
            for (int m = 0; m < 8; m++) {
                float4 av = *(const float4*)(&sXF[(wg * 8 + m) * 128 + k]);
                GEMM_STEP_F2(acc[m], av, w0, w1, w2, w3);
            }
        }
        float4 inv4 = *(const float4*)(&sInv[c0]);
        #pragma unroll
        for (int m = 0; m < 8; m++) {
            const int row = wg * 8 + m;
            float4 v = make_float4(0.f, 0.f, 0.f, 0.f);
            if (valid[m]) {
                float4 xfv = *(const float4*)(&sXF[row * 128 + c0]);
                float2 lo = unpack2(acc[m][0]);
                float2 hi = unpack2(acc[m][1]);
                v.x = __expf(xfv.x) * inv4.x * fmaxf(lo.x, 0.f);
                v.y = __expf(xfv.y) * inv4.y * fmaxf(lo.y, 0.f);
                v.z = __expf(xfv.z) * inv4.z * fmaxf(hi.x, 0.f);
                v.w = __expf(xfv.w) * inv4.w * fmaxf(hi.y, 0.f);
            }
            *(float4*)(&sAXI[row * 128 + c0]) = v;
        }
        __syncwarp();
    }

    // ---- stage B: g = relu(h @ Wo1 + bo1); out = g @ Wo2 + bo2 ----
    float rsum[8];
    #pragma unroll
    for (int m = 0; m < 8; m++) rsum[m] = 0.f;

    #pragma unroll
    for (int half = 0; half < 2; half++) {
        const int n0 = half * 128 + c0;
        u64 g[8][2];
        {
            ulonglong2 bias = *(const ulonglong2*)(bo1 + n0);
            #pragma unroll
            for (int m = 0; m < 8; m++) { g[m][0] = bias.x; g[m][1] = bias.y; }
        }
        // xf part: Wo1 rows 128..255
        for (int k = 0; k < 128; k += 4) {
            ulonglong2 w0 = *(const ulonglong2*)(Wo1 + (128 + k + 0) * 256 + n0);
            ulonglong2 w1 = *(const ulonglong2*)(Wo1 + (128 + k + 1) * 256 + n0);
            ulonglong2 w2 = *(const ulonglong2*)(Wo1 + (128 + k + 2) * 256 + n0);
            ulonglong2 w3 = *(const ulonglong2*)(Wo1 + (128 + k + 3) * 256 + n0);
            #pragma unroll
            for (int m = 0; m < 8; m++) {
                float4 av = *(const float4*)(&sXF[(wg * 8 + m) * 128 + k]);
                GEMM_STEP_F2(g[m], av, w0, w1, w2, w3);
            }
        }
        // a*x_inner part: Wo1 rows 0..127 (skipped when no valid row in warp)
        if (any) {
            for (int k = 0; k < 128; k += 4) {
                ulonglong2 w0 = *(const ulonglong2*)(Wo1 + (k + 0) * 256 + n0);
                ulonglong2 w1 = *(const ulonglong2*)(Wo1 + (k + 1) * 256 + n0);
                ulonglong2 w2 = *(const ulonglong2*)(Wo1 + (k + 2) * 256 + n0);
                ulonglong2 w3 = *(const ulonglong2*)(Wo1 + (k + 3) * 256 + n0);
                #pragma unroll
                for (int m = 0; m < 8; m++) {
                    float4 av = *(const float4*)(&sAXI[(wg * 8 + m) * 128 + k]);
                    GEMM_STEP_F2(g[m], av, w0, w1, w2, w3);
                }
            }
        }
        float4 w2v = *(const float4*)(Wo2 + n0);
        #pragma unroll
        for (int m = 0; m < 8; m++) {
            float2 lo = unpack2(g[m][0]);
            float2 hi = unpack2(g[m][1]);
            rsum[m] += fmaxf(lo.x, 0.f) * w2v.x + fmaxf(lo.y, 0.f) * w2v.y
                     + fmaxf(hi.x, 0.f) * w2v.z + fmaxf(hi.y, 0.f) * w2v.w;
        }
    }

    #pragma unroll
    for (int off = 16; off; off >>= 1) {
        #pragma unroll
        for (int m = 0; m < 8; m++)
            rsum[m] += __shfl_xor_sync(0xffffffffu, rsum[m], off);
    }
    if (cg == 0) {
        const float b2 = bo2[0];
        #pragma unroll
        for (int m = 0; m < 8; m++)
            out[row0 + wg * 8 + m] = rsum[m] + b2;
    }
}

// ---------------------------------------------------------------------------
extern "C" void kernel_launch(void* const* d_in, const int* in_sizes, int n_in,
                              void* d_out, int out_size) {
    const float* x          = (const float*)d_in[0];
    const unsigned char* mk = (const unsigned char*)d_in[1];
    const float* Wi1        = (const float*)d_in[2];
    const float* bi1        = (const float*)d_in[3];
    const float* Wi2        = (const float*)d_in[4];
    const float* bi2        = (const float*)d_in[5];
    const float* We         = (const float*)d_in[6];
    const float* Wo1        = (const float*)d_in[7];
    const float* bo1        = (const float*)d_in[8];
    const float* Wo2        = (const float*)d_in[9];
    const float* bo2        = (const float*)d_in[10];
    float* out              = (float*)d_out;

    const int smem_k_out = (2 * 64 * 128 + 128) * (int)sizeof(float);  // 66 KB
    cudaFuncSetAttribute(k_out, cudaFuncAttributeMaxDynamicSharedMemorySize, smem_k_out);

    k_setup<<<1, 512>>>(mk);
    k_embed<<<RT / 64, 256>>>(x, Wi1, bi1, Wi2, bi2);
    k_out<<<RT / 64, 256, smem_k_out>>>(We, Wo1, bo1, Wo2, bo2, out);
}